// round 8
// baseline (speedup 1.0000x reference)
#include <cuda_runtime.h>
#include <cuda_bf16.h>
#include <math.h>
#include <cstdint>

#define S_LEN 2048
#define DH    64
#define NELEM (2 * 16 * 2048 * 64)
#define LOG2E 1.4426950408889634f

// bf16 hi/lo scratch: Q (pre-scaled by log2e), K rope'd; V plain. [bh][s][d].
__device__ __align__(16) __nv_bfloat16 g_Qhi[NELEM], g_Qlo[NELEM];
__device__ __align__(16) __nv_bfloat16 g_Khi[NELEM], g_Klo[NELEM];
__device__ __align__(16) __nv_bfloat16 g_Vhi[NELEM], g_Vlo[NELEM];

// ---------------------------------------------------------------------------
// helpers
// ---------------------------------------------------------------------------
__device__ __forceinline__ uint32_t smem_u32(const void* p) {
    uint32_t a;
    asm("{ .reg .u64 t; cvta.to.shared.u64 t, %1; cvt.u32.u64 %0, t; }" : "=r"(a) : "l"(p));
    return a;
}
__device__ __forceinline__ void cp16(uint32_t dst, const void* src) {
    asm volatile("cp.async.cg.shared.global [%0], [%1], 16;" :: "r"(dst), "l"(src));
}
__device__ __forceinline__ void cp_commit() { asm volatile("cp.async.commit_group;"); }
template <int N>
__device__ __forceinline__ void cp_wait() { asm volatile("cp.async.wait_group %0;" :: "n"(N)); }

__device__ __forceinline__ void ldsm4(uint32_t r[4], uint32_t a) {
    asm volatile("ldmatrix.sync.aligned.m8n8.x4.shared.b16 {%0,%1,%2,%3}, [%4];"
                 : "=r"(r[0]), "=r"(r[1]), "=r"(r[2]), "=r"(r[3]) : "r"(a));
}
__device__ __forceinline__ void ldsm4t(uint32_t r[4], uint32_t a) {
    asm volatile("ldmatrix.sync.aligned.m8n8.x4.trans.shared.b16 {%0,%1,%2,%3}, [%4];"
                 : "=r"(r[0]), "=r"(r[1]), "=r"(r[2]), "=r"(r[3]) : "r"(a));
}
// NOTE: non-volatile — lets ptxas interleave independent HMMA chains.
__device__ __forceinline__ void mma_bf16(float c[4], const uint32_t a[4],
                                         uint32_t b0, uint32_t b1) {
    asm("mma.sync.aligned.m16n8k16.row.col.f32.bf16.bf16.f32 "
        "{%0,%1,%2,%3}, {%4,%5,%6,%7}, {%8,%9}, {%0,%1,%2,%3};"
        : "+f"(c[0]), "+f"(c[1]), "+f"(c[2]), "+f"(c[3])
        : "r"(a[0]), "r"(a[1]), "r"(a[2]), "r"(a[3]), "r"(b0), "r"(b1));
}
__device__ __forceinline__ float ex2(float x) {
    float y;
    asm("ex2.approx.f32 %0, %1;" : "=f"(y) : "f"(x));
    return y;
}
__device__ __forceinline__ uint32_t pack_hi(float a, float b, float& ra, float& rb) {
    __nv_bfloat16 ha = __float2bfloat16_rn(a), hb = __float2bfloat16_rn(b);
    ra = a - __bfloat162float(ha);
    rb = b - __bfloat162float(hb);
    return (uint32_t)__bfloat16_as_ushort(ha) | ((uint32_t)__bfloat16_as_ushort(hb) << 16);
}
__device__ __forceinline__ uint32_t pack_bf(float a, float b) {
    return (uint32_t)__bfloat16_as_ushort(__float2bfloat16_rn(a)) |
           ((uint32_t)__bfloat16_as_ushort(__float2bfloat16_rn(b)) << 16);
}

// ---------------------------------------------------------------------------
// Fused prep: RoPE+split Q (x log2e), K; split V. One thread per (even,odd).
// ---------------------------------------------------------------------------
__global__ void prep_kernel(const float* __restrict__ Q, const float* __restrict__ K,
                            const float* __restrict__ V, int pairs) {
    int idx = blockIdx.x * blockDim.x + threadIdx.x;
    if (idx >= pairs) return;
    int i = idx & 31, bhs = idx >> 5, s = bhs & (S_LEN - 1);
    float div = expf((float)(2 * i) * (-logf(10000.0f) / (float)DH));
    float sn, cs;
    sincosf((float)s * div, &sn, &cs);
    size_t base = (size_t)bhs * DH + 2 * i;

    float qe = Q[base], qo = Q[base + 1];
    float q0 = (qe * cs - qo * sn) * LOG2E;
    float q1 = (qe * sn + qo * cs) * LOG2E;
    float r0, r1;
    *(uint32_t*)&g_Qhi[base] = pack_hi(q0, q1, r0, r1);
    *(uint32_t*)&g_Qlo[base] = pack_bf(r0, r1);

    float ke = K[base], ko = K[base + 1];
    float k0 = ke * cs - ko * sn, k1 = ke * sn + ko * cs;
    *(uint32_t*)&g_Khi[base] = pack_hi(k0, k1, r0, r1);
    *(uint32_t*)&g_Klo[base] = pack_bf(r0, r1);

    float2 v = *(const float2*)&V[base];
    *(uint32_t*)&g_Vhi[base] = pack_hi(v.x, v.y, r0, r1);
    *(uint32_t*)&g_Vlo[base] = pack_bf(r0, r1);
}

// ---------------------------------------------------------------------------
// Flash attention, mma.sync bf16x3, no-rescale softmax (exp2-domain scores).
// Grid (16, 32). 256 threads. Interleaved dual-accumulator MMA issue.
// ---------------------------------------------------------------------------
#define SM_QHI   0
#define SM_QLO   16384
#define SM_KV    32768
#define KVBUF    32768
#define SM_BYTES 98304

__global__ __launch_bounds__(256, 2) void attn_kernel(float* __restrict__ O) {
    extern __shared__ __align__(1024) char smem[];
    const uint32_t sb = smem_u32(smem);
    const int tid  = threadIdx.x;
    const int lane = tid & 31;
    const int warp = tid >> 5;
    const int mr   = warp * 16;
    const int qt   = 15 - blockIdx.x;
    const int bh   = blockIdx.y;
    const size_t hoff = (size_t)bh * S_LEN * DH;
    const int ntiles = 2 * qt + 2;

    // group A: Q tiles (2048 x 16B)
    {
        const char* gQh = (const char*)(g_Qhi + hoff + (size_t)qt * 128 * DH);
        const char* gQl = (const char*)(g_Qlo + hoff + (size_t)qt * 128 * DH);
#pragma unroll
        for (int t = 0; t < 8; t++) {
            int i = tid + t * 256;
            int arr = i >> 10, idx = i & 1023;
            int r = idx >> 3, cs = (idx & 7) << 4;
            const char* g = arr ? gQl : gQh;
            cp16(sb + SM_QHI + arr * 16384 + r * 128 + (cs ^ ((r & 7) << 4)),
                 g + r * 128 + cs);
        }
        cp_commit();
    }
    // group B: KV tile 0
    {
        const char* kh = (const char*)(g_Khi + hoff);
        const char* kl = (const char*)(g_Klo + hoff);
        const char* vh = (const char*)(g_Vhi + hoff);
        const char* vl = (const char*)(g_Vlo + hoff);
#pragma unroll
        for (int t = 0; t < 8; t++) {
            int i = tid + t * 256;
            int arr = i >> 9, idx = i & 511;
            int r = idx >> 3, cs = (idx & 7) << 4;
            const char* g = (arr == 0) ? kh : (arr == 1) ? kl : (arr == 2) ? vh : vl;
            cp16(sb + SM_KV + arr * 8192 + r * 128 + (cs ^ ((r & 7) << 4)),
                 g + r * 128 + cs);
        }
        cp_commit();
    }

    // ---- per-lane ldmatrix address components ----
    const int ar  = mr + (lane & 15);
    const int acs = ((lane >> 4) & 1) << 4;
    const uint32_t asw = (ar & 7) << 4;
    const uint32_t qhi_row = sb + SM_QHI + ar * 128;
    const uint32_t qlo_row = sb + SM_QLO + ar * 128;
    const int ki = lane >> 3, kr = lane & 7;
    const uint32_t krow_off  = (uint32_t)(((ki >> 1) * 8 + kr) * 128);
    const uint32_t khalf_sel = (uint32_t)((ki & 1) << 4);
    const uint32_t krsw      = (uint32_t)(kr << 4);
    const int vi = lane >> 3, vr = lane & 7;
    const uint32_t vrow_off = (uint32_t)(((vi & 1) * 8 + vr) * 128);
    const uint32_t vdsel    = (uint32_t)(vi >> 1);
    const uint32_t vrsw     = (uint32_t)(vr << 4);

    cp_wait<1>();          // Q (group A) complete
    __syncthreads();

    // hoist Q fragments (loop-invariant)
    uint32_t qh[4][4], ql[4][4];
#pragma unroll
    for (int kc = 0; kc < 4; kc++) {
        const uint32_t aoff = (uint32_t)(((kc << 5) | acs) ^ asw);
        ldsm4(qh[kc], qhi_row + aoff);
        ldsm4(ql[kc], qlo_row + aoff);
    }

    float o[8][4];
#pragma unroll
    for (int j = 0; j < 8; j++)
#pragma unroll
        for (int e = 0; e < 4; e++) o[j][e] = 0.0f;
    float lsum0 = 0.0f, lsum1 = 0.0f;

    const int r0g = qt * 128 + mr + (lane >> 2);
    const int cb0 = 2 * (lane & 3);

    for (int it = 0; it < ntiles; it++) {
        if (it + 1 < ntiles) {
            const uint32_t nb = sb + SM_KV + (uint32_t)((it + 1) & 1) * KVBUF;
            const char* kh = (const char*)(g_Khi + hoff + (size_t)(it + 1) * 64 * DH);
            const char* kl = (const char*)(g_Klo + hoff + (size_t)(it + 1) * 64 * DH);
            const char* vh = (const char*)(g_Vhi + hoff + (size_t)(it + 1) * 64 * DH);
            const char* vl = (const char*)(g_Vlo + hoff + (size_t)(it + 1) * 64 * DH);
#pragma unroll
            for (int t = 0; t < 8; t++) {
                int i = tid + t * 256;
                int arr = i >> 9, idx = i & 511;
                int r = idx >> 3, cs = (idx & 7) << 4;
                const char* g = (arr == 0) ? kh : (arr == 1) ? kl : (arr == 2) ? vh : vl;
                cp16(nb + arr * 8192 + r * 128 + (cs ^ ((r & 7) << 4)), g + r * 128 + cs);
            }
            cp_commit();
            cp_wait<1>();
        } else {
            cp_wait<0>();
        }
        __syncthreads();

        const uint32_t kvb = sb + SM_KV + (uint32_t)(it & 1) * KVBUF;
        const uint32_t sKh = kvb, sKl = kvb + 8192, sVh = kvb + 16384, sVl = kvb + 24576;

        // ---- S = Q K^T (bf16x3), dual-accumulator interleave ----
        float c[8][4];
#pragma unroll
        for (int j = 0; j < 8; j++)
#pragma unroll
            for (int e = 0; e < 4; e++) c[j][e] = 0.0f;

#pragma unroll
        for (int kc = 0; kc < 4; kc++) {
            const uint32_t koff = (((uint32_t)(kc << 5)) | khalf_sel) ^ krsw;
#pragma unroll
            for (int jp = 0; jp < 4; jp++) {
                uint32_t k4h[4], k4l[4];
                const uint32_t kb_ = (uint32_t)(jp << 11) + krow_off + koff;
                ldsm4(k4h, sKh + kb_);
                ldsm4(k4l, sKl + kb_);
                mma_bf16(c[2 * jp],     qh[kc], k4h[0], k4h[1]);
                mma_bf16(c[2 * jp + 1], qh[kc], k4h[2], k4h[3]);
                mma_bf16(c[2 * jp],     qh[kc], k4l[0], k4l[1]);
                mma_bf16(c[2 * jp + 1], qh[kc], k4l[2], k4l[3]);
                mma_bf16(c[2 * jp],     ql[kc], k4h[0], k4h[1]);
                mma_bf16(c[2 * jp + 1], ql[kc], k4h[2], k4h[3]);
            }
        }

        // ---- per 16-wide k-chunk: mask + exp2 + pack P + PV MMA ----
        const int kb0 = it * 64 + cb0;
#pragma unroll
        for (int kc = 0; kc < 4; kc++) {
            const int j0 = 2 * kc, j1 = 2 * kc + 1;
            const int cj0 = kb0 + 8 * j0, cj1 = kb0 + 8 * j1;
            float ra, rb;
            uint32_t Ah[4], Al[4];

            float e0 = (cj0     <= r0g)     ? ex2(c[j0][0]) : 0.0f;
            float e1 = (cj0 + 1 <= r0g)     ? ex2(c[j0][1]) : 0.0f;
            float e2 = (cj0     <= r0g + 8) ? ex2(c[j0][2]) : 0.0f;
            float e3 = (cj0 + 1 <= r0g + 8) ? ex2(c[j0][3]) : 0.0f;
            lsum0 += e0 + e1;
            lsum1 += e2 + e3;
            Ah[0] = pack_hi(e0, e1, ra, rb); Al[0] = pack_bf(ra, rb);
            Ah[1] = pack_hi(e2, e3, ra, rb); Al[1] = pack_bf(ra, rb);

            float f0 = (cj1     <= r0g)     ? ex2(c[j1][0]) : 0.0f;
            float f1 = (cj1 + 1 <= r0g)     ? ex2(c[j1][1]) : 0.0f;
            float f2 = (cj1     <= r0g + 8) ? ex2(c[j1][2]) : 0.0f;
            float f3 = (cj1 + 1 <= r0g + 8) ? ex2(c[j1][3]) : 0.0f;
            lsum0 += f0 + f1;
            lsum1 += f2 + f3;
            Ah[2] = pack_hi(f0, f1, ra, rb); Al[2] = pack_bf(ra, rb);
            Ah[3] = pack_hi(f2, f3, ra, rb); Al[3] = pack_bf(ra, rb);

            const uint32_t vb_ = (uint32_t)(kc << 11) + vrow_off;
#pragma unroll
            for (int jp = 0; jp < 4; jp++) {
                uint32_t v4h[4], v4l[4];
                const uint32_t va = vb_ + ((((uint32_t)(2 * jp) + vdsel) << 4) ^ vrsw);
                ldsm4t(v4h, sVh + va);
                ldsm4t(v4l, sVl + va);
                mma_bf16(o[2 * jp],     Ah, v4h[0], v4h[1]);
                mma_bf16(o[2 * jp + 1], Ah, v4h[2], v4h[3]);
                mma_bf16(o[2 * jp],     Ah, v4l[0], v4l[1]);
                mma_bf16(o[2 * jp + 1], Ah, v4l[2], v4l[3]);
                mma_bf16(o[2 * jp],     Al, v4h[0], v4h[1]);
                mma_bf16(o[2 * jp + 1], Al, v4h[2], v4h[3]);
            }
        }
        __syncthreads();   // all warps done with this KV buffer
    }

    // ---- epilogue ----
    float l0 = lsum0, l1 = lsum1;
    l0 += __shfl_xor_sync(0xffffffffu, l0, 1);
    l0 += __shfl_xor_sync(0xffffffffu, l0, 2);
    l1 += __shfl_xor_sync(0xffffffffu, l1, 1);
    l1 += __shfl_xor_sync(0xffffffffu, l1, 2);
    const float inv0 = 1.0f / l0;
    const float inv1 = 1.0f / l1;
    float* ob0 = O + hoff + (size_t)r0g * DH;
    float* ob1 = ob0 + 8 * DH;
#pragma unroll
    for (int j = 0; j < 8; j++) {
        float2 w0 = {o[j][0] * inv0, o[j][1] * inv0};
        float2 w1 = {o[j][2] * inv1, o[j][3] * inv1};
        *(float2*)&ob0[j * 8 + cb0] = w0;
        *(float2*)&ob1[j * 8 + cb0] = w1;
    }
}

// ---------------------------------------------------------------------------
extern "C" void kernel_launch(void* const* d_in, const int* in_sizes, int n_in,
                              void* d_out, int out_size) {
    const float* Q = (const float*)d_in[0];
    const float* K = (const float*)d_in[1];
    const float* V = (const float*)d_in[2];
    float* O = (float*)d_out;

    int pairs = in_sizes[0] / 2;
    prep_kernel<<<(pairs + 255) / 256, 256>>>(Q, K, V, pairs);

    cudaFuncSetAttribute(attn_kernel, cudaFuncAttributeMaxDynamicSharedMemorySize, SM_BYTES);
    attn_kernel<<<dim3(16, 32), 256, SM_BYTES>>>(O);
}

// round 10
// speedup vs baseline: 1.1425x; 1.1425x over previous
#include <cuda_runtime.h>
#include <cuda_bf16.h>
#include <math.h>
#include <cstdint>

#define S_LEN 2048
#define DH    64
#define NELEM (2 * 16 * 2048 * 64)
#define LOG2E 1.4426950408889634f

// bf16 hi/lo scratch: Q (pre-scaled by log2e), K rope'd; V plain. [bh][s][d].
__device__ __align__(16) __nv_bfloat16 g_Qhi[NELEM], g_Qlo[NELEM];
__device__ __align__(16) __nv_bfloat16 g_Khi[NELEM], g_Klo[NELEM];
__device__ __align__(16) __nv_bfloat16 g_Vhi[NELEM], g_Vlo[NELEM];

// ---------------------------------------------------------------------------
// helpers
// ---------------------------------------------------------------------------
__device__ __forceinline__ uint32_t smem_u32(const void* p) {
    uint32_t a;
    asm("{ .reg .u64 t; cvta.to.shared.u64 t, %1; cvt.u32.u64 %0, t; }" : "=r"(a) : "l"(p));
    return a;
}
__device__ __forceinline__ void cp16(uint32_t dst, const void* src) {
    asm volatile("cp.async.cg.shared.global [%0], [%1], 16;" :: "r"(dst), "l"(src));
}
__device__ __forceinline__ void cp_commit() { asm volatile("cp.async.commit_group;"); }
template <int N>
__device__ __forceinline__ void cp_wait() { asm volatile("cp.async.wait_group %0;" :: "n"(N)); }

__device__ __forceinline__ void ldsm4(uint32_t r[4], uint32_t a) {
    asm volatile("ldmatrix.sync.aligned.m8n8.x4.shared.b16 {%0,%1,%2,%3}, [%4];"
                 : "=r"(r[0]), "=r"(r[1]), "=r"(r[2]), "=r"(r[3]) : "r"(a));
}
__device__ __forceinline__ void ldsm4t(uint32_t r[4], uint32_t a) {
    asm volatile("ldmatrix.sync.aligned.m8n8.x4.trans.shared.b16 {%0,%1,%2,%3}, [%4];"
                 : "=r"(r[0]), "=r"(r[1]), "=r"(r[2]), "=r"(r[3]) : "r"(a));
}
// non-volatile: ptxas may schedule freely (register-only effects)
__device__ __forceinline__ void mma_bf16(float c[4], const uint32_t a[4],
                                         uint32_t b0, uint32_t b1) {
    asm("mma.sync.aligned.m16n8k16.row.col.f32.bf16.bf16.f32 "
        "{%0,%1,%2,%3}, {%4,%5,%6,%7}, {%8,%9}, {%0,%1,%2,%3};"
        : "+f"(c[0]), "+f"(c[1]), "+f"(c[2]), "+f"(c[3])
        : "r"(a[0]), "r"(a[1]), "r"(a[2]), "r"(a[3]), "r"(b0), "r"(b1));
}
__device__ __forceinline__ float ex2(float x) {
    float y;
    asm("ex2.approx.f32 %0, %1;" : "=f"(y) : "f"(x));
    return y;
}
// packed bf16x2 convert: result = {lo16 = bf16(a), hi16 = bf16(b)}
__device__ __forceinline__ uint32_t cvt_bf2(float a, float b) {
    uint32_t r;
    asm("cvt.rn.bf16x2.f32 %0, %1, %2;" : "=r"(r) : "f"(b), "f"(a));
    return r;
}
// hi/lo split of a pair in 6 instructions
__device__ __forceinline__ void pack_pair(float a, float b, uint32_t& hi, uint32_t& lo) {
    hi = cvt_bf2(a, b);
    float ha = __uint_as_float(hi << 16);
    float hb = __uint_as_float(hi & 0xFFFF0000u);
    lo = cvt_bf2(a - ha, b - hb);
}

// ---------------------------------------------------------------------------
// Fused prep: RoPE+split Q (x log2e), K; split V. One thread per (even,odd).
// ---------------------------------------------------------------------------
__global__ void prep_kernel(const float* __restrict__ Q, const float* __restrict__ K,
                            const float* __restrict__ V, int pairs) {
    int idx = blockIdx.x * blockDim.x + threadIdx.x;
    if (idx >= pairs) return;
    int i = idx & 31, bhs = idx >> 5, s = bhs & (S_LEN - 1);
    float div = expf((float)(2 * i) * (-logf(10000.0f) / (float)DH));
    float sn, cs;
    sincosf((float)s * div, &sn, &cs);
    size_t base = (size_t)bhs * DH + 2 * i;

    float qe = Q[base], qo = Q[base + 1];
    float q0 = (qe * cs - qo * sn) * LOG2E;
    float q1 = (qe * sn + qo * cs) * LOG2E;
    uint32_t h, l;
    pack_pair(q0, q1, h, l);
    *(uint32_t*)&g_Qhi[base] = h;
    *(uint32_t*)&g_Qlo[base] = l;

    float ke = K[base], ko = K[base + 1];
    float k0 = ke * cs - ko * sn, k1 = ke * sn + ko * cs;
    pack_pair(k0, k1, h, l);
    *(uint32_t*)&g_Khi[base] = h;
    *(uint32_t*)&g_Klo[base] = l;

    float2 v = *(const float2*)&V[base];
    pack_pair(v.x, v.y, h, l);
    *(uint32_t*)&g_Vhi[base] = h;
    *(uint32_t*)&g_Vlo[base] = l;
}

// ---------------------------------------------------------------------------
// Flash attention, mma.sync bf16x3, no-rescale softmax (exp2-domain scores).
// Grid (16, 32). 256 threads. Reduced register pressure + cheap packs +
// mask-free fast path on fully-unmasked (warp,tile) pairs.
// ---------------------------------------------------------------------------
#define SM_QHI   0
#define SM_QLO   16384
#define SM_KV    32768
#define KVBUF    32768
#define SM_BYTES 98304

__global__ __launch_bounds__(256, 2) void attn_kernel(float* __restrict__ O) {
    extern __shared__ __align__(1024) char smem[];
    const uint32_t sb = smem_u32(smem);
    const int tid  = threadIdx.x;
    const int lane = tid & 31;
    const int warp = tid >> 5;
    const int mr   = warp * 16;
    const int qt   = 15 - blockIdx.x;
    const int bh   = blockIdx.y;
    const size_t hoff = (size_t)bh * S_LEN * DH;
    const int ntiles = 2 * qt + 2;

    // group A: Q tiles (2048 x 16B)
    {
        const char* gQh = (const char*)(g_Qhi + hoff + (size_t)qt * 128 * DH);
        const char* gQl = (const char*)(g_Qlo + hoff + (size_t)qt * 128 * DH);
#pragma unroll
        for (int t = 0; t < 8; t++) {
            int i = tid + t * 256;
            int arr = i >> 10, idx = i & 1023;
            int r = idx >> 3, cs = (idx & 7) << 4;
            const char* g = arr ? gQl : gQh;
            cp16(sb + SM_QHI + arr * 16384 + r * 128 + (cs ^ ((r & 7) << 4)),
                 g + r * 128 + cs);
        }
        cp_commit();
    }
    // group B: KV tile 0
    {
        const char* kh = (const char*)(g_Khi + hoff);
        const char* kl = (const char*)(g_Klo + hoff);
        const char* vh = (const char*)(g_Vhi + hoff);
        const char* vl = (const char*)(g_Vlo + hoff);
#pragma unroll
        for (int t = 0; t < 8; t++) {
            int i = tid + t * 256;
            int arr = i >> 9, idx = i & 511;
            int r = idx >> 3, cs = (idx & 7) << 4;
            const char* g = (arr == 0) ? kh : (arr == 1) ? kl : (arr == 2) ? vh : vl;
            cp16(sb + SM_KV + arr * 8192 + r * 128 + (cs ^ ((r & 7) << 4)),
                 g + r * 128 + cs);
        }
        cp_commit();
    }

    // ---- per-lane ldmatrix address components ----
    const int ar  = mr + (lane & 15);
    const int acs = ((lane >> 4) & 1) << 4;
    const uint32_t asw = (ar & 7) << 4;
    const uint32_t qhi_row = sb + SM_QHI + ar * 128;
    const uint32_t qlo_row = sb + SM_QLO + ar * 128;
    const int ki = lane >> 3, kr = lane & 7;
    const uint32_t krow_off  = (uint32_t)(((ki >> 1) * 8 + kr) * 128);
    const uint32_t khalf_sel = (uint32_t)((ki & 1) << 4);
    const uint32_t krsw      = (uint32_t)(kr << 4);
    const int vi = lane >> 3, vr = lane & 7;
    const uint32_t vrow_off = (uint32_t)(((vi & 1) * 8 + vr) * 128);
    const uint32_t vdsel    = (uint32_t)(vi >> 1);
    const uint32_t vrsw     = (uint32_t)(vr << 4);

    cp_wait<1>();          // Q (group A) complete
    __syncthreads();

    // hoist Q-hi fragments only (Q-lo reloaded per tile: saves 16 regs)
    uint32_t qh[4][4];
#pragma unroll
    for (int kc = 0; kc < 4; kc++)
        ldsm4(qh[kc], qhi_row + (uint32_t)(((kc << 5) | acs) ^ asw));

    float o[8][4];
#pragma unroll
    for (int j = 0; j < 8; j++)
#pragma unroll
        for (int e = 0; e < 4; e++) o[j][e] = 0.0f;
    float lsum0 = 0.0f, lsum1 = 0.0f;

    const int r0g = qt * 128 + mr + (lane >> 2);
    const int cb0 = 2 * (lane & 3);

    for (int it = 0; it < ntiles; it++) {
        if (it + 1 < ntiles) {
            const uint32_t nb = sb + SM_KV + (uint32_t)((it + 1) & 1) * KVBUF;
            const char* kh = (const char*)(g_Khi + hoff + (size_t)(it + 1) * 64 * DH);
            const char* kl = (const char*)(g_Klo + hoff + (size_t)(it + 1) * 64 * DH);
            const char* vh = (const char*)(g_Vhi + hoff + (size_t)(it + 1) * 64 * DH);
            const char* vl = (const char*)(g_Vlo + hoff + (size_t)(it + 1) * 64 * DH);
#pragma unroll
            for (int t = 0; t < 8; t++) {
                int i = tid + t * 256;
                int arr = i >> 9, idx = i & 511;
                int r = idx >> 3, cs = (idx & 7) << 4;
                const char* g = (arr == 0) ? kh : (arr == 1) ? kl : (arr == 2) ? vh : vl;
                cp16(nb + arr * 8192 + r * 128 + (cs ^ ((r & 7) << 4)), g + r * 128 + cs);
            }
            cp_commit();
            cp_wait<1>();
        } else {
            cp_wait<0>();
        }
        __syncthreads();

        const uint32_t kvb = sb + SM_KV + (uint32_t)(it & 1) * KVBUF;
        const uint32_t sKh = kvb, sKl = kvb + 8192, sVh = kvb + 16384, sVl = kvb + 24576;

        // ---- S = Q K^T (bf16x3) ----
        float c[8][4];
#pragma unroll
        for (int j = 0; j < 8; j++)
#pragma unroll
            for (int e = 0; e < 4; e++) c[j][e] = 0.0f;

#pragma unroll
        for (int kc = 0; kc < 4; kc++) {
            const uint32_t koff = (((uint32_t)(kc << 5)) | khalf_sel) ^ krsw;
            uint32_t ql[4];
            ldsm4(ql, qlo_row + (uint32_t)(((kc << 5) | acs) ^ asw));
#pragma unroll
            for (int jp = 0; jp < 4; jp++) {
                uint32_t k4h[4], k4l[4];
                const uint32_t kb_ = (uint32_t)(jp << 11) + krow_off + koff;
                ldsm4(k4h, sKh + kb_);
                ldsm4(k4l, sKl + kb_);
                mma_bf16(c[2 * jp],     qh[kc], k4h[0], k4h[1]);
                mma_bf16(c[2 * jp + 1], qh[kc], k4h[2], k4h[3]);
                mma_bf16(c[2 * jp],     qh[kc], k4l[0], k4l[1]);
                mma_bf16(c[2 * jp + 1], qh[kc], k4l[2], k4l[3]);
                mma_bf16(c[2 * jp],     ql,     k4h[0], k4h[1]);
                mma_bf16(c[2 * jp + 1], ql,     k4h[2], k4h[3]);
            }
        }

        // ---- softmax + PV, per 16-wide k-chunk ----
        const int kb0 = it * 64 + cb0;
        const bool unmasked = (it * 64 + 63 <= qt * 128 + mr);   // warp-uniform
#pragma unroll
        for (int kc = 0; kc < 4; kc++) {
            const int j0 = 2 * kc, j1 = 2 * kc + 1;
            float e0, e1, e2, e3, f0, f1, f2, f3;
            if (unmasked) {
                e0 = ex2(c[j0][0]); e1 = ex2(c[j0][1]);
                e2 = ex2(c[j0][2]); e3 = ex2(c[j0][3]);
                f0 = ex2(c[j1][0]); f1 = ex2(c[j1][1]);
                f2 = ex2(c[j1][2]); f3 = ex2(c[j1][3]);
            } else {
                const int cj0 = kb0 + 8 * j0, cj1 = kb0 + 8 * j1;
                e0 = (cj0     <= r0g)     ? ex2(c[j0][0]) : 0.0f;
                e1 = (cj0 + 1 <= r0g)     ? ex2(c[j0][1]) : 0.0f;
                e2 = (cj0     <= r0g + 8) ? ex2(c[j0][2]) : 0.0f;
                e3 = (cj0 + 1 <= r0g + 8) ? ex2(c[j0][3]) : 0.0f;
                f0 = (cj1     <= r0g)     ? ex2(c[j1][0]) : 0.0f;
                f1 = (cj1 + 1 <= r0g)     ? ex2(c[j1][1]) : 0.0f;
                f2 = (cj1     <= r0g + 8) ? ex2(c[j1][2]) : 0.0f;
                f3 = (cj1 + 1 <= r0g + 8) ? ex2(c[j1][3]) : 0.0f;
            }
            lsum0 += (e0 + e1) + (f0 + f1);
            lsum1 += (e2 + e3) + (f2 + f3);

            uint32_t Ah[4], Al[4];
            pack_pair(e0, e1, Ah[0], Al[0]);
            pack_pair(e2, e3, Ah[1], Al[1]);
            pack_pair(f0, f1, Ah[2], Al[2]);
            pack_pair(f2, f3, Ah[3], Al[3]);

            const uint32_t vb_ = (uint32_t)(kc << 11) + vrow_off;
#pragma unroll
            for (int jp = 0; jp < 4; jp++) {
                uint32_t v4h[4], v4l[4];
                const uint32_t va = vb_ + ((((uint32_t)(2 * jp) + vdsel) << 4) ^ vrsw);
                ldsm4t(v4h, sVh + va);
                ldsm4t(v4l, sVl + va);
                mma_bf16(o[2 * jp],     Ah, v4h[0], v4h[1]);
                mma_bf16(o[2 * jp + 1], Ah, v4h[2], v4h[3]);
                mma_bf16(o[2 * jp],     Ah, v4l[0], v4l[1]);
                mma_bf16(o[2 * jp + 1], Ah, v4l[2], v4l[3]);
                mma_bf16(o[2 * jp],     Al, v4h[0], v4h[1]);
                mma_bf16(o[2 * jp + 1], Al, v4h[2], v4h[3]);
            }
        }
        __syncthreads();   // all warps done with this KV buffer
    }

    // ---- epilogue ----
    float l0 = lsum0, l1 = lsum1;
    l0 += __shfl_xor_sync(0xffffffffu, l0, 1);
    l0 += __shfl_xor_sync(0xffffffffu, l0, 2);
    l1 += __shfl_xor_sync(0xffffffffu, l1, 1);
    l1 += __shfl_xor_sync(0xffffffffu, l1, 2);
    const float inv0 = 1.0f / l0;
    const float inv1 = 1.0f / l1;
    float* ob0 = O + hoff + (size_t)r0g * DH;
    float* ob1 = ob0 + 8 * DH;
#pragma unroll
    for (int j = 0; j < 8; j++) {
        float2 w0 = {o[j][0] * inv0, o[j][1] * inv0};
        float2 w1 = {o[j][2] * inv1, o[j][3] * inv1};
        *(float2*)&ob0[j * 8 + cb0] = w0;
        *(float2*)&ob1[j * 8 + cb0] = w1;
    }
}

// ---------------------------------------------------------------------------
extern "C" void kernel_launch(void* const* d_in, const int* in_sizes, int n_in,
                              void* d_out, int out_size) {
    const float* Q = (const float*)d_in[0];
    const float* K = (const float*)d_in[1];
    const float* V = (const float*)d_in[2];
    float* O = (float*)d_out;

    int pairs = in_sizes[0] / 2;
    prep_kernel<<<(pairs + 255) / 256, 256>>>(Q, K, V, pairs);

    cudaFuncSetAttribute(attn_kernel, cudaFuncAttributeMaxDynamicSharedMemorySize, SM_BYTES);
    attn_kernel<<<dim3(16, 32), 256, SM_BYTES>>>(O);
}

// round 11
// speedup vs baseline: 1.1634x; 1.0182x over previous
#include <cuda_runtime.h>
#include <cuda_bf16.h>
#include <math.h>
#include <cstdint>

#define S_LEN 2048
#define DH    64
#define NELEM (2 * 16 * 2048 * 64)
#define LOG2E 1.4426950408889634f

// bf16 hi/lo scratch: Q (pre-scaled by log2e), K rope'd; V plain. [bh][s][d].
__device__ __align__(16) __nv_bfloat16 g_Qhi[NELEM], g_Qlo[NELEM];
__device__ __align__(16) __nv_bfloat16 g_Khi[NELEM], g_Klo[NELEM];
__device__ __align__(16) __nv_bfloat16 g_Vhi[NELEM], g_Vlo[NELEM];

// ---------------------------------------------------------------------------
// helpers
// ---------------------------------------------------------------------------
__device__ __forceinline__ uint32_t smem_u32(const void* p) {
    uint32_t a;
    asm("{ .reg .u64 t; cvta.to.shared.u64 t, %1; cvt.u32.u64 %0, t; }" : "=r"(a) : "l"(p));
    return a;
}
__device__ __forceinline__ void cp16(uint32_t dst, const void* src) {
    asm volatile("cp.async.cg.shared.global [%0], [%1], 16;" :: "r"(dst), "l"(src));
}
__device__ __forceinline__ void cp_commit() { asm volatile("cp.async.commit_group;"); }
template <int N>
__device__ __forceinline__ void cp_wait() { asm volatile("cp.async.wait_group %0;" :: "n"(N)); }

__device__ __forceinline__ void ldsm4(uint32_t r[4], uint32_t a) {
    asm volatile("ldmatrix.sync.aligned.m8n8.x4.shared.b16 {%0,%1,%2,%3}, [%4];"
                 : "=r"(r[0]), "=r"(r[1]), "=r"(r[2]), "=r"(r[3]) : "r"(a));
}
__device__ __forceinline__ void ldsm4t(uint32_t r[4], uint32_t a) {
    asm volatile("ldmatrix.sync.aligned.m8n8.x4.trans.shared.b16 {%0,%1,%2,%3}, [%4];"
                 : "=r"(r[0]), "=r"(r[1]), "=r"(r[2]), "=r"(r[3]) : "r"(a));
}
// non-volatile: ptxas may schedule freely (register-only effects)
__device__ __forceinline__ void mma_bf16(float c[4], const uint32_t a[4],
                                         uint32_t b0, uint32_t b1) {
    asm("mma.sync.aligned.m16n8k16.row.col.f32.bf16.bf16.f32 "
        "{%0,%1,%2,%3}, {%4,%5,%6,%7}, {%8,%9}, {%0,%1,%2,%3};"
        : "+f"(c[0]), "+f"(c[1]), "+f"(c[2]), "+f"(c[3])
        : "r"(a[0]), "r"(a[1]), "r"(a[2]), "r"(a[3]), "r"(b0), "r"(b1));
}
__device__ __forceinline__ float ex2(float x) {
    float y;
    asm("ex2.approx.f32 %0, %1;" : "=f"(y) : "f"(x));
    return y;
}
// packed bf16x2 convert: result = {lo16 = bf16(a), hi16 = bf16(b)}
__device__ __forceinline__ uint32_t cvt_bf2(float a, float b) {
    uint32_t r;
    asm("cvt.rn.bf16x2.f32 %0, %1, %2;" : "=r"(r) : "f"(b), "f"(a));
    return r;
}
// hi/lo split of a pair in 6 instructions
__device__ __forceinline__ void pack_pair(float a, float b, uint32_t& hi, uint32_t& lo) {
    hi = cvt_bf2(a, b);
    float ha = __uint_as_float(hi << 16);
    float hb = __uint_as_float(hi & 0xFFFF0000u);
    lo = cvt_bf2(a - ha, b - hb);
}

// ---------------------------------------------------------------------------
// Fused prep: RoPE+split Q (x log2e), K; split V. One thread per (even,odd).
// ---------------------------------------------------------------------------
__global__ void prep_kernel(const float* __restrict__ Q, const float* __restrict__ K,
                            const float* __restrict__ V, int pairs) {
    int idx = blockIdx.x * blockDim.x + threadIdx.x;
    if (idx >= pairs) return;
    int i = idx & 31, bhs = idx >> 5, s = bhs & (S_LEN - 1);
    float div = expf((float)(2 * i) * (-logf(10000.0f) / (float)DH));
    float sn, cs;
    sincosf((float)s * div, &sn, &cs);
    size_t base = (size_t)bhs * DH + 2 * i;

    float qe = Q[base], qo = Q[base + 1];
    float q0 = (qe * cs - qo * sn) * LOG2E;
    float q1 = (qe * sn + qo * cs) * LOG2E;
    uint32_t h, l;
    pack_pair(q0, q1, h, l);
    *(uint32_t*)&g_Qhi[base] = h;
    *(uint32_t*)&g_Qlo[base] = l;

    float ke = K[base], ko = K[base + 1];
    float k0 = ke * cs - ko * sn, k1 = ke * sn + ko * cs;
    pack_pair(k0, k1, h, l);
    *(uint32_t*)&g_Khi[base] = h;
    *(uint32_t*)&g_Klo[base] = l;

    float2 v = *(const float2*)&V[base];
    pack_pair(v.x, v.y, h, l);
    *(uint32_t*)&g_Vhi[base] = h;
    *(uint32_t*)&g_Vlo[base] = l;
}

// ---------------------------------------------------------------------------
// Flash attention, mma.sync bf16x3, no-rescale softmax (exp2-domain scores).
// Grid (16, 32). 256 threads. Fused QK->softmax->PV per n-pair keeps score
// live range at 8 regs; Q hi+lo fragments hoisted; streamlined cp.async.
// ---------------------------------------------------------------------------
#define SM_QHI   0
#define SM_QLO   16384
#define SM_KV    32768
#define KVBUF    32768
#define SM_BYTES 98304

__global__ __launch_bounds__(256, 2) void attn_kernel(float* __restrict__ O) {
    extern __shared__ __align__(1024) char smem[];
    const uint32_t sb = smem_u32(smem);
    const int tid  = threadIdx.x;
    const int lane = tid & 31;
    const int warp = tid >> 5;
    const int mr   = warp * 16;
    const int qt   = 15 - blockIdx.x;
    const int bh   = blockIdx.y;
    const size_t hoff = (size_t)bh * S_LEN * DH;
    const int ntiles = 2 * qt + 2;

    // ---- streamlined KV staging: thread owns one array, 8 chunks @ stride 1024
    const int a64 = tid >> 6, t64 = tid & 63;
    const char* kv_src = (const char*)((a64 == 0) ? (const void*)(g_Khi + hoff)
                        : (a64 == 1) ? (const void*)(g_Klo + hoff)
                        : (a64 == 2) ? (const void*)(g_Vhi + hoff)
                                     : (const void*)(g_Vlo + hoff))
                        + t64 * 16;
    const uint32_t kv_dst = sb + SM_KV +
        (uint32_t)(a64 * 8192 + (t64 >> 3) * 128 + (((t64 & 7) << 4) ^ ((t64 >> 3) << 4)));

    // group A: Q tiles (2048 x 16B)
    {
        const char* gQh = (const char*)(g_Qhi + hoff + (size_t)qt * 128 * DH);
        const char* gQl = (const char*)(g_Qlo + hoff + (size_t)qt * 128 * DH);
#pragma unroll
        for (int t = 0; t < 8; t++) {
            int i = tid + t * 256;
            int arr = i >> 10, idx = i & 1023;
            int r = idx >> 3, cs = (idx & 7) << 4;
            const char* g = arr ? gQl : gQh;
            cp16(sb + SM_QHI + arr * 16384 + r * 128 + (cs ^ ((r & 7) << 4)),
                 g + r * 128 + cs);
        }
        cp_commit();
    }
    // group B: KV tile 0
    {
#pragma unroll
        for (int j = 0; j < 8; j++)
            cp16(kv_dst + (uint32_t)(j * 1024), kv_src + j * 1024);
        cp_commit();
    }

    // ---- per-lane ldmatrix address components ----
    const int ar  = mr + (lane & 15);
    const int acs = ((lane >> 4) & 1) << 4;
    const uint32_t asw = (ar & 7) << 4;
    const int ki = lane >> 3, kr = lane & 7;
    const uint32_t krow_off  = (uint32_t)(((ki >> 1) * 8 + kr) * 128);
    const uint32_t khalf_sel = (uint32_t)((ki & 1) << 4);
    const uint32_t krsw      = (uint32_t)(kr << 4);
    const int vi = lane >> 3, vr = lane & 7;
    const uint32_t vrow_off = (uint32_t)(((vi & 1) * 8 + vr) * 128);
    const uint32_t vdsel    = (uint32_t)(vi >> 1);
    const uint32_t vrsw     = (uint32_t)(vr << 4);

    cp_wait<1>();          // Q (group A) complete
    __syncthreads();

    // hoist Q hi+lo fragments (loop-invariant)
    uint32_t qh[4][4], ql[4][4];
    {
        const uint32_t qhi_row = sb + SM_QHI + ar * 128;
        const uint32_t qlo_row = sb + SM_QLO + ar * 128;
#pragma unroll
        for (int kc = 0; kc < 4; kc++) {
            const uint32_t aoff = (uint32_t)(((kc << 5) | acs) ^ asw);
            ldsm4(qh[kc], qhi_row + aoff);
            ldsm4(ql[kc], qlo_row + aoff);
        }
    }

    float o[8][4];
#pragma unroll
    for (int j = 0; j < 8; j++)
#pragma unroll
        for (int e = 0; e < 4; e++) o[j][e] = 0.0f;
    float lsum0 = 0.0f, lsum1 = 0.0f;

    const int r0g = qt * 128 + mr + (lane >> 2);
    const int cb0 = 2 * (lane & 3);

    for (int it = 0; it < ntiles; it++) {
        if (it + 1 < ntiles) {
            const uint32_t nb = kv_dst + (uint32_t)((it + 1) & 1) * KVBUF;
            const char* src = kv_src + (size_t)(it + 1) * 8192;
#pragma unroll
            for (int j = 0; j < 8; j++)
                cp16(nb + (uint32_t)(j * 1024), src + j * 1024);
            cp_commit();
            cp_wait<1>();
        } else {
            cp_wait<0>();
        }
        __syncthreads();

        const uint32_t kvb = sb + SM_KV + (uint32_t)(it & 1) * KVBUF;
        const uint32_t sKh = kvb, sKl = kvb + 8192, sVh = kvb + 16384, sVl = kvb + 24576;

        const int kb0 = it * 64 + cb0;
        const bool unmasked = (it * 64 + 63 <= qt * 128 + mr);   // warp-uniform

        // ---- fused per n-pair: QK (bf16x3) -> softmax -> PV ----
#pragma unroll
        for (int jp = 0; jp < 4; jp++) {
            // QK for n-tiles 2jp, 2jp+1 over all 4 k-chunks
            float c0[4] = {0.f, 0.f, 0.f, 0.f};
            float c1[4] = {0.f, 0.f, 0.f, 0.f};
            const uint32_t kbase = (uint32_t)(jp << 11) + krow_off;
#pragma unroll
            for (int kc = 0; kc < 4; kc++) {
                uint32_t k4h[4], k4l[4];
                const uint32_t kb_ = kbase + ((((uint32_t)(kc << 5)) | khalf_sel) ^ krsw);
                ldsm4(k4h, sKh + kb_);
                ldsm4(k4l, sKl + kb_);
                mma_bf16(c0, qh[kc], k4h[0], k4h[1]);
                mma_bf16(c1, qh[kc], k4h[2], k4h[3]);
                mma_bf16(c0, qh[kc], k4l[0], k4l[1]);
                mma_bf16(c1, qh[kc], k4l[2], k4l[3]);
                mma_bf16(c0, ql[kc], k4h[0], k4h[1]);
                mma_bf16(c1, ql[kc], k4h[2], k4h[3]);
            }

            // softmax for this 16-wide k-chunk
            float e0, e1, e2, e3, f0, f1, f2, f3;
            if (unmasked) {
                e0 = ex2(c0[0]); e1 = ex2(c0[1]); e2 = ex2(c0[2]); e3 = ex2(c0[3]);
                f0 = ex2(c1[0]); f1 = ex2(c1[1]); f2 = ex2(c1[2]); f3 = ex2(c1[3]);
            } else {
                const int cj0 = kb0 + 16 * jp, cj1 = cj0 + 8;
                e0 = (cj0     <= r0g)     ? ex2(c0[0]) : 0.0f;
                e1 = (cj0 + 1 <= r0g)     ? ex2(c0[1]) : 0.0f;
                e2 = (cj0     <= r0g + 8) ? ex2(c0[2]) : 0.0f;
                e3 = (cj0 + 1 <= r0g + 8) ? ex2(c0[3]) : 0.0f;
                f0 = (cj1     <= r0g)     ? ex2(c1[0]) : 0.0f;
                f1 = (cj1 + 1 <= r0g)     ? ex2(c1[1]) : 0.0f;
                f2 = (cj1     <= r0g + 8) ? ex2(c1[2]) : 0.0f;
                f3 = (cj1 + 1 <= r0g + 8) ? ex2(c1[3]) : 0.0f;
            }
            lsum0 += (e0 + e1) + (f0 + f1);
            lsum1 += (e2 + e3) + (f2 + f3);

            uint32_t Ah[4], Al[4];
            pack_pair(e0, e1, Ah[0], Al[0]);
            pack_pair(e2, e3, Ah[1], Al[1]);
            pack_pair(f0, f1, Ah[2], Al[2]);
            pack_pair(f2, f3, Ah[3], Al[3]);

            // PV: P k-chunk jp into all 8 d-tile accumulators
            const uint32_t vb_ = (uint32_t)(jp << 11) + vrow_off;
#pragma unroll
            for (int dp = 0; dp < 4; dp++) {
                uint32_t v4h[4], v4l[4];
                const uint32_t va = vb_ + ((((uint32_t)(2 * dp) + vdsel) << 4) ^ vrsw);
                ldsm4t(v4h, sVh + va);
                ldsm4t(v4l, sVl + va);
                mma_bf16(o[2 * dp],     Ah, v4h[0], v4h[1]);
                mma_bf16(o[2 * dp + 1], Ah, v4h[2], v4h[3]);
                mma_bf16(o[2 * dp],     Ah, v4l[0], v4l[1]);
                mma_bf16(o[2 * dp + 1], Ah, v4l[2], v4l[3]);
                mma_bf16(o[2 * dp],     Al, v4h[0], v4h[1]);
                mma_bf16(o[2 * dp + 1], Al, v4h[2], v4h[3]);
            }
        }
        __syncthreads();   // all warps done with this KV buffer
    }

    // ---- epilogue ----
    float l0 = lsum0, l1 = lsum1;
    l0 += __shfl_xor_sync(0xffffffffu, l0, 1);
    l0 += __shfl_xor_sync(0xffffffffu, l0, 2);
    l1 += __shfl_xor_sync(0xffffffffu, l1, 1);
    l1 += __shfl_xor_sync(0xffffffffu, l1, 2);
    const float inv0 = 1.0f / l0;
    const float inv1 = 1.0f / l1;
    float* ob0 = O + hoff + (size_t)r0g * DH;
    float* ob1 = ob0 + 8 * DH;
#pragma unroll
    for (int j = 0; j < 8; j++) {
        float2 w0 = {o[j][0] * inv0, o[j][1] * inv0};
        float2 w1 = {o[j][2] * inv1, o[j][3] * inv1};
        *(float2*)&ob0[j * 8 + cb0] = w0;
        *(float2*)&ob1[j * 8 + cb0] = w1;
    }
}

// ---------------------------------------------------------------------------
extern "C" void kernel_launch(void* const* d_in, const int* in_sizes, int n_in,
                              void* d_out, int out_size) {
    const float* Q = (const float*)d_in[0];
    const float* K = (const float*)d_in[1];
    const float* V = (const float*)d_in[2];
    float* O = (float*)d_out;

    int pairs = in_sizes[0] / 2;
    prep_kernel<<<(pairs + 255) / 256, 256>>>(Q, K, V, pairs);

    cudaFuncSetAttribute(attn_kernel, cudaFuncAttributeMaxDynamicSharedMemorySize, SM_BYTES);
    attn_kernel<<<dim3(16, 32), 256, SM_BYTES>>>(O);
}